// round 3
// baseline (speedup 1.0000x reference)
#include <cuda_runtime.h>

#define NN 50000
#define EE 800000
#define HH 64

// ---------------- device scratch (no allocation allowed) ----------------
__device__ __align__(16) float g_y[(size_t)NN * HH];     // pre-aggregation features y = A @ Wa
__device__ __align__(16) float g_agg[(size_t)NN * HH];   // (1+eps)*y + bias, then scatter-added
__device__ __align__(16) float g_u[(size_t)NN * HH];     // post-MLP2 activations (BN input)
__device__ double g_sum[HH];               // BN column sums
__device__ double g_sq[HH];                // BN column sum of squares
__device__ int g_ei32;                     // 1 if edge_index is int32, 0 if int64

__global__ void reset_sums_kernel() {
    int t = threadIdx.x;
    if (t < HH) { g_sum[t] = 0.0; g_sq[t] = 0.0; }
}

// Probe edge_index dtype. For int64 (little-endian, values < 2^31) every odd
// 32-bit word is the zero high-half; for int32 the odd words are random node
// ids in [0, N) — 64 samples all being zero is ~impossible. Deterministic.
__global__ void detect_dtype_kernel(const int* __restrict__ ei) {
    if (threadIdx.x == 0) {
        int nz = 0;
#pragma unroll
        for (int i = 0; i < 64; i++) nz |= ei[2 * i + 1];
        g_ei32 = (nz != 0) ? 1 : 0;
    }
}

// ---------------- fused GEMM ----------------
// C[M x 64] = act(A[M x KDIM]) @ W[KDIM x 64]
// ACT: 0 = identity, 1 = relu, 2 = BN-affine(from g_sum/g_sq) + relu
// EPI: 0 = write Y=C and AGG=(1+eps)*C + bias   (pre-aggregation epilogue)
//      1 = U = relu(C + bias), write U(->Y arg), accumulate BN sums
template<int KDIM, int ACT, int EPI>
__global__ __launch_bounds__(256) void gemm_kernel(
    const float* __restrict__ A, const float* __restrict__ W,
    const float* __restrict__ bias, const float* __restrict__ epsp,
    const float* __restrict__ bng, const float* __restrict__ bnb,
    float* __restrict__ Y, float* __restrict__ AGG)
{
    __shared__ __align__(16) float w_sh[KDIM * 64];
    __shared__ __align__(16) float a_sh[16 * 132];
    __shared__ float bnsc[64];
    __shared__ float bnsh[64];
    __shared__ float bsum[64];
    __shared__ float bsq[64];

    const int tid = threadIdx.x;

    for (int i = tid; i < KDIM * 64; i += 256) w_sh[i] = W[i];
    if (ACT == 2) {
        if (tid < 64) {
            double m = g_sum[tid] / (double)NN;
            double v = g_sq[tid] / (double)NN - m * m;
            float sc = bng[tid] * rsqrtf((float)v + 1e-5f);
            bnsc[tid] = sc;
            bnsh[tid] = bnb[tid] - (float)m * sc;
        }
    }
    if (EPI == 1 && tid < 64) { bsum[tid] = 0.f; bsq[tid] = 0.f; }
    __syncthreads();

    const int row0 = blockIdx.x * 128;
    const int r0 = (tid >> 4) * 8;
    const int c0 = (tid & 15) * 4;

    float acc[8][4];
#pragma unroll
    for (int i = 0; i < 8; i++)
#pragma unroll
        for (int j = 0; j < 4; j++) acc[i][j] = 0.f;

    for (int k0 = 0; k0 < KDIM; k0 += 16) {
        // stage A tile (transposed, activated) into shared
#pragma unroll
        for (int rep = 0; rep < 2; rep++) {
            int lin = tid + rep * 256;   // 0..511
            int row = lin >> 2;          // 0..127
            int c4 = lin & 3;            // 0..3
            int grow = row0 + row;
            float4 v = make_float4(0.f, 0.f, 0.f, 0.f);
            if (grow < NN)
                v = *(const float4*)(A + (size_t)grow * KDIM + k0 + c4 * 4);
            if (ACT == 1) {
                v.x = fmaxf(v.x, 0.f); v.y = fmaxf(v.y, 0.f);
                v.z = fmaxf(v.z, 0.f); v.w = fmaxf(v.w, 0.f);
            } else if (ACT == 2) {
                int kb = k0 + c4 * 4;
                v.x = fmaxf(fmaf(v.x, bnsc[kb + 0], bnsh[kb + 0]), 0.f);
                v.y = fmaxf(fmaf(v.y, bnsc[kb + 1], bnsh[kb + 1]), 0.f);
                v.z = fmaxf(fmaf(v.z, bnsc[kb + 2], bnsh[kb + 2]), 0.f);
                v.w = fmaxf(fmaf(v.w, bnsc[kb + 3], bnsh[kb + 3]), 0.f);
            }
            a_sh[(c4 * 4 + 0) * 132 + row] = v.x;
            a_sh[(c4 * 4 + 1) * 132 + row] = v.y;
            a_sh[(c4 * 4 + 2) * 132 + row] = v.z;
            a_sh[(c4 * 4 + 3) * 132 + row] = v.w;
        }
        __syncthreads();
#pragma unroll
        for (int kk = 0; kk < 16; kk++) {
            float4 a0 = *(const float4*)(a_sh + kk * 132 + r0);
            float4 a1 = *(const float4*)(a_sh + kk * 132 + r0 + 4);
            float4 wv = *(const float4*)(w_sh + (k0 + kk) * 64 + c0);
            float av[8] = {a0.x, a0.y, a0.z, a0.w, a1.x, a1.y, a1.z, a1.w};
            float wl[4] = {wv.x, wv.y, wv.z, wv.w};
#pragma unroll
            for (int i = 0; i < 8; i++)
#pragma unroll
                for (int j = 0; j < 4; j++)
                    acc[i][j] = fmaf(av[i], wl[j], acc[i][j]);
        }
        __syncthreads();
    }

    if (EPI == 0) {
        float ep = 1.0f + *epsp;
        float4 bv = *(const float4*)(bias + c0);
#pragma unroll
        for (int i = 0; i < 8; i++) {
            int grow = row0 + r0 + i;
            if (grow < NN) {
                float4 yv = make_float4(acc[i][0], acc[i][1], acc[i][2], acc[i][3]);
                *(float4*)(Y + (size_t)grow * 64 + c0) = yv;
                float4 av = make_float4(fmaf(yv.x, ep, bv.x), fmaf(yv.y, ep, bv.y),
                                        fmaf(yv.z, ep, bv.z), fmaf(yv.w, ep, bv.w));
                *(float4*)(AGG + (size_t)grow * 64 + c0) = av;
            }
        }
    } else {
        float4 bv = *(const float4*)(bias + c0);
        float ps[4] = {0.f, 0.f, 0.f, 0.f};
        float pq[4] = {0.f, 0.f, 0.f, 0.f};
#pragma unroll
        for (int i = 0; i < 8; i++) {
            int grow = row0 + r0 + i;
            if (grow < NN) {
                float u0 = fmaxf(acc[i][0] + bv.x, 0.f);
                float u1 = fmaxf(acc[i][1] + bv.y, 0.f);
                float u2 = fmaxf(acc[i][2] + bv.z, 0.f);
                float u3 = fmaxf(acc[i][3] + bv.w, 0.f);
                *(float4*)(Y + (size_t)grow * 64 + c0) = make_float4(u0, u1, u2, u3);
                ps[0] += u0; ps[1] += u1; ps[2] += u2; ps[3] += u3;
                pq[0] += u0 * u0; pq[1] += u1 * u1; pq[2] += u2 * u2; pq[3] += u3 * u3;
            }
        }
        atomicAdd(&bsum[c0 + 0], ps[0]); atomicAdd(&bsum[c0 + 1], ps[1]);
        atomicAdd(&bsum[c0 + 2], ps[2]); atomicAdd(&bsum[c0 + 3], ps[3]);
        atomicAdd(&bsq[c0 + 0], pq[0]); atomicAdd(&bsq[c0 + 1], pq[1]);
        atomicAdd(&bsq[c0 + 2], pq[2]); atomicAdd(&bsq[c0 + 3], pq[3]);
        __syncthreads();
        if (tid < 64) {
            atomicAdd(&g_sum[tid], (double)bsum[tid]);
            atomicAdd(&g_sq[tid], (double)bsq[tid]);
        }
    }
}

// ---------------- scatter-add over edges ----------------
// agg[dst] += y[src]; 16 threads/edge, one float4 red each.
__global__ __launch_bounds__(256) void scatter_kernel(const void* __restrict__ eiv)
{
    int t = blockIdx.x * 256 + threadIdx.x;
    int e = t >> 4;
    int c = t & 15;
    if (e >= EE) return;
    int s, d;
    if (g_ei32) {
        const int* ei = (const int*)eiv;
        s = ei[e];
        d = ei[EE + e];
    } else {
        const long long* ei = (const long long*)eiv;
        s = (int)ei[e];
        d = (int)ei[EE + e];
    }
    float4 v = ((const float4*)g_y)[(size_t)s * 16 + c];
    float* p = g_agg + ((size_t)d * 64 + c * 4);
    asm volatile("red.global.add.v4.f32 [%0], {%1,%2,%3,%4};"
                 :: "l"(p), "f"(v.x), "f"(v.y), "f"(v.z), "f"(v.w)
                 : "memory");
}

// ---------------- final: out = bn_relu(u3) @ lin_w + lin_b ----------------
__global__ __launch_bounds__(128) void final_kernel(
    const float* __restrict__ bng, const float* __restrict__ bnb,
    const float* __restrict__ lw, const float* __restrict__ lb,
    float* __restrict__ out)
{
    __shared__ float a_sh[128 * 65];
    __shared__ float w_sh[64 * 10];
    __shared__ float b_sh[10];
    __shared__ float bnsc[64];
    __shared__ float bnsh[64];

    int tid = threadIdx.x;
    if (tid < 64) {
        double m = g_sum[tid] / (double)NN;
        double v = g_sq[tid] / (double)NN - m * m;
        float sc = bng[tid] * rsqrtf((float)v + 1e-5f);
        bnsc[tid] = sc;
        bnsh[tid] = bnb[tid] - (float)m * sc;
    }
    for (int i = tid; i < 640; i += 128) w_sh[i] = lw[i];
    if (tid < 10) b_sh[tid] = lb[tid];
    __syncthreads();

    int row0 = blockIdx.x * 128;
    for (int idx = tid; idx < 128 * 64; idx += 128) {
        int r = idx >> 6;
        int k = idx & 63;
        int grow = row0 + r;
        float val = 0.f;
        if (grow < NN) val = g_u[(size_t)grow * 64 + k];
        a_sh[r * 65 + k] = fmaxf(fmaf(val, bnsc[k], bnsh[k]), 0.f);
    }
    __syncthreads();

    int grow = row0 + tid;
    if (grow < NN) {
        float a[64];
#pragma unroll
        for (int k = 0; k < 64; k++) a[k] = a_sh[tid * 65 + k];
        float accv[10];
#pragma unroll
        for (int c = 0; c < 10; c++) accv[c] = b_sh[c];
#pragma unroll
        for (int k = 0; k < 64; k++)
#pragma unroll
            for (int c = 0; c < 10; c++)
                accv[c] = fmaf(a[k], w_sh[k * 10 + c], accv[c]);
#pragma unroll
        for (int c = 0; c < 10; c++) out[(size_t)grow * 10 + c] = accv[c];
    }
}

// ---------------- launch ----------------
extern "C" void kernel_launch(void* const* d_in, const int* in_sizes, int n_in,
                              void* d_out, int out_size)
{
    const float* x       = (const float*)d_in[0];
    const void*  ei      = d_in[1];
    const float* eps1    = (const float*)d_in[2];
    const float* w1a     = (const float*)d_in[3];
    const float* b1a     = (const float*)d_in[4];
    const float* w1b     = (const float*)d_in[5];
    const float* b1b     = (const float*)d_in[6];
    const float* g1      = (const float*)d_in[7];
    const float* be1     = (const float*)d_in[8];
    const float* eps2    = (const float*)d_in[9];
    const float* w2a     = (const float*)d_in[10];
    const float* b2a     = (const float*)d_in[11];
    const float* w2b     = (const float*)d_in[12];
    const float* b2b     = (const float*)d_in[13];
    const float* g2      = (const float*)d_in[14];
    const float* be2     = (const float*)d_in[15];
    const float* eps3    = (const float*)d_in[16];
    const float* w3a     = (const float*)d_in[17];
    const float* b3a     = (const float*)d_in[18];
    const float* w3b     = (const float*)d_in[19];
    const float* b3b     = (const float*)d_in[20];
    const float* g3      = (const float*)d_in[21];
    const float* be3     = (const float*)d_in[22];
    const float* lin_w   = (const float*)d_in[23];
    const float* lin_b   = (const float*)d_in[24];
    float* out = (float*)d_out;

    float *yp = nullptr, *ap = nullptr, *up = nullptr;
    cudaGetSymbolAddress((void**)&yp, g_y);
    cudaGetSymbolAddress((void**)&ap, g_agg);
    cudaGetSymbolAddress((void**)&up, g_u);

    const int gemm_blocks = (NN + 127) / 128;          // 391
    const int scat_blocks = (EE * 16) / 256;           // 50000

    detect_dtype_kernel<<<1, 32>>>((const int*)ei);

    // ---- layer 1 ----
    gemm_kernel<128, 0, 0><<<gemm_blocks, 256>>>(x, w1a, b1a, eps1, nullptr, nullptr, yp, ap);
    scatter_kernel<<<scat_blocks, 256>>>(ei);
    reset_sums_kernel<<<1, 64>>>();
    gemm_kernel<64, 1, 1><<<gemm_blocks, 256>>>(ap, w1b, b1b, nullptr, nullptr, nullptr, up, nullptr);

    // ---- layer 2 ----
    gemm_kernel<64, 2, 0><<<gemm_blocks, 256>>>(up, w2a, b2a, eps2, g1, be1, yp, ap);
    scatter_kernel<<<scat_blocks, 256>>>(ei);
    reset_sums_kernel<<<1, 64>>>();
    gemm_kernel<64, 1, 1><<<gemm_blocks, 256>>>(ap, w2b, b2b, nullptr, nullptr, nullptr, up, nullptr);

    // ---- layer 3 ----
    gemm_kernel<64, 2, 0><<<gemm_blocks, 256>>>(up, w3a, b3a, eps3, g2, be2, yp, ap);
    scatter_kernel<<<scat_blocks, 256>>>(ei);
    reset_sums_kernel<<<1, 64>>>();
    gemm_kernel<64, 1, 1><<<gemm_blocks, 256>>>(ap, w3b, b3b, nullptr, nullptr, nullptr, up, nullptr);

    // ---- classifier ----
    final_kernel<<<gemm_blocks, 128>>>(g3, be3, lin_w, lin_b, out);
}